// round 15
// baseline (speedup 1.0000x reference)
#include <cuda_runtime.h>
#include <cstdint>

// ScaledPredictionLayer, B = 2^21 rows (~293 MB streamed).
// R7: cp.async double-buffer -> 49.6us @ DRAM 80%. This version: 3-stage
// cp.async pipeline (2 tiles in flight per block), ONE barrier per tile,
// 4 blocks/SM x 152 SMs, dynamic smem 52.2 KB.

constexpr int TPB   = 128;
constexpr int ROWS  = 128;                 // rows per tile
constexpr int PP_F4 = ROWS * 7;            // 896 float4 (pred tile, 14336 B)
constexpr int SP_F4 = (ROWS * 6) / 4;      // 192 float4 (scaled tile, 3072 B)
constexpr int TILE_F4 = PP_F4 + SP_F4;     // 1088 float4 = 17408 B per buffer
constexpr int NBUF  = 3;
constexpr int SMEM_BYTES = NBUF * TILE_F4 * 16;   // 52224 B

__device__ __forceinline__ uint32_t smem_u32(const void* p) {
    return (uint32_t)__cvta_generic_to_shared(p);
}
__device__ __forceinline__ void cp16(uint32_t dst, const void* src) {
    asm volatile("cp.async.cg.shared.global [%0], [%1], 16;" :: "r"(dst), "l"(src) : "memory");
}
__device__ __forceinline__ void cp8(uint32_t dst, const void* src) {
    asm volatile("cp.async.ca.shared.global [%0], [%1], 8;" :: "r"(dst), "l"(src) : "memory");
}
__device__ __forceinline__ void cp_commit() {
    asm volatile("cp.async.commit_group;" ::: "memory");
}
__device__ __forceinline__ void cp_wait1() {   // allow 1 group pending -> oldest forced done
    asm volatile("cp.async.wait_group 1;" ::: "memory");
}

__global__ __launch_bounds__(TPB) void scaled_pred_kernel(
    const float* __restrict__ sp,      // (B, 6)
    const float* __restrict__ pp,      // (B, 28)
    const float* __restrict__ pmean,   // (6,)
    const float* __restrict__ pscale,  // (6,)
    const float* __restrict__ tmean,   // (1,)
    const float* __restrict__ tscale,  // (1,)
    float* __restrict__ out,           // (B,)
    int B)
{
    extern __shared__ float4 smem[];       // [NBUF][TILE_F4]

    const int tid    = threadIdx.x;
    const int ntiles = (B + ROWS - 1) / ROWS;

    // ---- broadcast vectors, hoisted ----
    float pm[6], psc[6];
#pragma unroll
    for (int i = 0; i < 6; i++) { pm[i] = __ldg(pmean + i); psc[i] = __ldg(pscale + i); }
    const float tm     = __ldg(tmean);
    const float inv_ts = 1.0f / __ldg(tscale);

    auto prefetch = [&](int t, int slot) {
        const uint32_t base = smem_u32(&smem[slot * TILE_F4]);
        const int rem = min(ROWS, B - t * ROWS);
        const float4* gpp = reinterpret_cast<const float4*>(pp + (size_t)t * ROWS * 28);
        if (rem == ROWS) {
            // full tile: static trip counts -> 9 back-to-back LDGSTS per thread
#pragma unroll
            for (int q = 0; q < PP_F4 / TPB; q++) {            // 7 iterations
                const int i = q * TPB + tid;
                cp16(base + (uint32_t)i * 16u, gpp + i);
            }
            const float4* gsp = reinterpret_cast<const float4*>(sp + (size_t)t * ROWS * 6);
            // SP_F4 = 192 = 128 + 64
            cp16(base + (uint32_t)(PP_F4 + tid) * 16u, gsp + tid);
            if (tid < SP_F4 - TPB)
                cp16(base + (uint32_t)(PP_F4 + TPB + tid) * 16u, gsp + TPB + tid);
        } else {
            // tail tile: row-exact granules
            const int npp = rem * 7;
            for (int i = tid; i < npp; i += TPB)
                cp16(base + (uint32_t)i * 16u, gpp + i);
            const float2* gsp2 = reinterpret_cast<const float2*>(sp + (size_t)t * ROWS * 6);
            const int nsp = rem * 3;
            for (int i = tid; i < nsp; i += TPB)
                cp8(base + (uint32_t)PP_F4 * 16u + (uint32_t)i * 8u, gsp2 + i);
        }
    };

    const int t0     = blockIdx.x;
    const int stride = gridDim.x;

    // ---- prologue: 2 tiles in flight ----
    if (t0 < ntiles) prefetch(t0, 0);
    cp_commit();
    if (t0 + stride < ntiles) prefetch(t0 + stride, 1);
    cp_commit();

    int slot = 0;
    for (int t = t0; t < ntiles; t += stride, slot = (slot + 1 == NBUF) ? 0 : slot + 1) {
        cp_wait1();            // pending {t, t+1} -> tile t's group forced complete
        __syncthreads();       // (a) t's data visible block-wide
                               // (b) fences last readers of the slot about to be refilled

        // issue t+2 into the slot whose readers finished last iteration
        const int tnn = t + 2 * stride;
        const int wslot = (slot + 2 >= NBUF) ? slot + 2 - NBUF : slot + 2;
        if (tnn < ntiles) prefetch(tnn, wslot);
        cp_commit();           // empty groups near the tail are fine

        const int rem = min(ROWS, B - t * ROWS);
        if (tid < rem) {
            const float* s_pp = reinterpret_cast<const float*>(&smem[slot * TILE_F4]);
            const float* s_sp = reinterpret_cast<const float*>(&smem[slot * TILE_F4 + PP_F4]);

            // own row: 7x LDS.128 at 112B stride -> conflict-free
            float p[28];
            const float4* pr = reinterpret_cast<const float4*>(s_pp + tid * 28);
#pragma unroll
            for (int q = 0; q < 7; q++) {
                float4 v = pr[q];
                p[4*q+0] = v.x; p[4*q+1] = v.y; p[4*q+2] = v.z; p[4*q+3] = v.w;
            }
            float s[6];
            {
                const float2* srw = reinterpret_cast<const float2*>(s_sp + tid * 6);
                float2 a = srw[0], b2 = srw[1], c2 = srw[2];
                s[0] = a.x; s[1] = a.y; s[2] = b2.x; s[3] = b2.y; s[4] = c2.x; s[5] = c2.y;
            }

            float dp[6];
#pragma unroll
            for (int i = 0; i < 6; i++)
                dp[i] = fmaf(s[i], psc[i], pm[i]) - p[1 + i];

            const float* c = p + 7;
            float maha = 0.0f;
            int k = 0;
#pragma unroll
            for (int i = 0; i < 6; i++) {
                maha = fmaf(c[k] * dp[i], dp[i], maha); k++;            // diagonal
#pragma unroll
                for (int j = i + 1; j < 6; j++) {
                    maha = fmaf(2.0f * c[k] * dp[i], dp[j], maha); k++; // off-diag x2
                }
            }

            out[t * ROWS + tid] = (fmaf(0.5f, maha, p[0]) - tm) * inv_ts;
        }
        // no trailing barrier: next iteration's post-wait barrier fences slot reuse
    }
}

extern "C" void kernel_launch(void* const* d_in, const int* in_sizes, int n_in,
                              void* d_out, int out_size)
{
    const float* sp     = (const float*)d_in[0];  // scaled_params (B,6)
    const float* pp     = (const float*)d_in[1];  // pred_params   (B,28)
    const float* pmean  = (const float*)d_in[2];  // (6,)
    const float* pscale = (const float*)d_in[3];  // (6,)
    const float* tmean  = (const float*)d_in[4];  // (1,)
    const float* tscale = (const float*)d_in[5];  // (1,)
    float* out = (float*)d_out;

    const int B      = in_sizes[0] / 6;
    const int ntiles = (B + ROWS - 1) / ROWS;

    // 52.2 KB dynamic smem -> opt-in (idempotent, capture-safe non-stream API)
    cudaFuncSetAttribute(scaled_pred_kernel,
                         cudaFuncAttributeMaxDynamicSharedMemorySize, SMEM_BYTES);

    // persistent grid: 4 blocks/SM on 152 SMs (GB300)
    int blocks = 152 * 4;
    if (blocks > ntiles) blocks = ntiles;
    scaled_pred_kernel<<<blocks, TPB, SMEM_BYTES>>>(sp, pp, pmean, pscale, tmean, tscale, out, B);
}

// round 16
// speedup vs baseline: 1.0223x; 1.0223x over previous
#include <cuda_runtime.h>
#include <cstdint>

// ScaledPredictionLayer, B = 2^21 rows (~293 MB streamed).
// R7 (proven): NBUF=2 cp.async pipeline, 888 blocks -> 49.6us @ DRAM 80.1%.
// R15 (failed): deeper pipeline but 608 blocks -> 77.0% (streams, not depth, bind).
// This version: SAME R7 pipeline, smaller tile (ROWS=TPB=96) -> 8 blocks/SM,
// grid 1216 = +37% independent streams. Static smem 26112 B.

constexpr int TPB   = 96;
constexpr int ROWS  = 96;                  // rows per tile
constexpr int PP_F4 = ROWS * 7;            // 672 float4 (pred tile, 10752 B)
constexpr int SP_F4 = (ROWS * 6) / 4;      // 144 float4 (scaled tile, 2304 B)
constexpr int TILE_F4 = PP_F4 + SP_F4;     // 816 float4 = 13056 B per buffer

__device__ __forceinline__ uint32_t smem_u32(const void* p) {
    return (uint32_t)__cvta_generic_to_shared(p);
}
__device__ __forceinline__ void cp16(uint32_t dst, const void* src) {
    asm volatile("cp.async.cg.shared.global [%0], [%1], 16;" :: "r"(dst), "l"(src) : "memory");
}
__device__ __forceinline__ void cp8(uint32_t dst, const void* src) {
    asm volatile("cp.async.ca.shared.global [%0], [%1], 8;" :: "r"(dst), "l"(src) : "memory");
}
__device__ __forceinline__ void cp_commit() {
    asm volatile("cp.async.commit_group;" ::: "memory");
}
__device__ __forceinline__ void cp_wait1() {   // allow 1 group pending -> oldest forced done
    asm volatile("cp.async.wait_group 1;" ::: "memory");
}

__global__ __launch_bounds__(TPB) void scaled_pred_kernel(
    const float* __restrict__ sp,      // (B, 6)
    const float* __restrict__ pp,      // (B, 28)
    const float* __restrict__ pmean,   // (6,)
    const float* __restrict__ pscale,  // (6,)
    const float* __restrict__ tmean,   // (1,)
    const float* __restrict__ tscale,  // (1,)
    float* __restrict__ out,           // (B,)
    int B)
{
    __shared__ float4 smem[2][TILE_F4];    // 26112 B static -> 8 blocks/SM

    const int tid    = threadIdx.x;
    const int ntiles = (B + ROWS - 1) / ROWS;

    // ---- broadcast vectors, hoisted ----
    float pm[6], psc[6];
#pragma unroll
    for (int i = 0; i < 6; i++) { pm[i] = __ldg(pmean + i); psc[i] = __ldg(pscale + i); }
    const float tm     = __ldg(tmean);
    const float inv_ts = 1.0f / __ldg(tscale);

    auto prefetch = [&](int t, int b) {
        const uint32_t base = smem_u32(&smem[b][0]);
        const int rem = min(ROWS, B - t * ROWS);
        const float4* gpp = reinterpret_cast<const float4*>(pp + (size_t)t * ROWS * 28);
        if (rem == ROWS) {
            // full tile: static trip counts -> 9 back-to-back LDGSTS per thread
#pragma unroll
            for (int q = 0; q < PP_F4 / TPB; q++) {            // 7 iterations (672/96)
                const int i = q * TPB + tid;
                cp16(base + (uint32_t)i * 16u, gpp + i);
            }
            const float4* gsp = reinterpret_cast<const float4*>(sp + (size_t)t * ROWS * 6);
            // SP_F4 = 144 = 96 + 48
            cp16(base + (uint32_t)(PP_F4 + tid) * 16u, gsp + tid);
            if (tid < SP_F4 - TPB)
                cp16(base + (uint32_t)(PP_F4 + TPB + tid) * 16u, gsp + TPB + tid);
        } else {
            // tail tile: row-exact granules (8B for sp so odd row counts can't overrun)
            const int npp = rem * 7;
            for (int i = tid; i < npp; i += TPB)
                cp16(base + (uint32_t)i * 16u, gpp + i);
            const float2* gsp2 = reinterpret_cast<const float2*>(sp + (size_t)t * ROWS * 6);
            const int nsp = rem * 3;
            for (int i = tid; i < nsp; i += TPB)
                cp8(base + (uint32_t)PP_F4 * 16u + (uint32_t)i * 8u, gsp2 + i);
        }
    };

    // ---- R7-proven pipeline: prefetch t0, then {prefetch next, wait cur, compute} ----
    const int t0     = blockIdx.x;
    const int stride = gridDim.x;

    if (t0 < ntiles) prefetch(t0, 0);
    cp_commit();

    int buf = 0;
    for (int t = t0; t < ntiles; t += stride) {
        const int tn = t + stride;
        if (tn < ntiles) prefetch(tn, buf ^ 1);
        cp_commit();           // (empty group on the final iteration is fine)
        cp_wait1();            // pending {t, t+1} -> tile t's group forced complete
        __syncthreads();       // copies from all threads visible block-wide

        const int rem = min(ROWS, B - t * ROWS);
        if (tid < rem) {
            const float* s_pp = reinterpret_cast<const float*>(&smem[buf][0]);
            const float* s_sp = reinterpret_cast<const float*>(&smem[buf][PP_F4]);

            // own row: 7x LDS.128 at 112B stride -> conflict-free
            float p[28];
            const float4* pr = reinterpret_cast<const float4*>(s_pp + tid * 28);
#pragma unroll
            for (int q = 0; q < 7; q++) {
                float4 v = pr[q];
                p[4*q+0] = v.x; p[4*q+1] = v.y; p[4*q+2] = v.z; p[4*q+3] = v.w;
            }
            float s[6];
            {
                const float2* srw = reinterpret_cast<const float2*>(s_sp + tid * 6);
                float2 a = srw[0], b2 = srw[1], c2 = srw[2];
                s[0] = a.x; s[1] = a.y; s[2] = b2.x; s[3] = b2.y; s[4] = c2.x; s[5] = c2.y;
            }

            float dp[6];
#pragma unroll
            for (int i = 0; i < 6; i++)
                dp[i] = fmaf(s[i], psc[i], pm[i]) - p[1 + i];

            const float* c = p + 7;
            float maha = 0.0f;
            int k = 0;
#pragma unroll
            for (int i = 0; i < 6; i++) {
                maha = fmaf(c[k] * dp[i], dp[i], maha); k++;            // diagonal
#pragma unroll
                for (int j = i + 1; j < 6; j++) {
                    maha = fmaf(2.0f * c[k] * dp[i], dp[j], maha); k++; // off-diag x2
                }
            }

            out[t * ROWS + tid] = (fmaf(0.5f, maha, p[0]) - tm) * inv_ts;
        }
        __syncthreads();       // all reads of this buffer done before refill
        buf ^= 1;
    }
}

extern "C" void kernel_launch(void* const* d_in, const int* in_sizes, int n_in,
                              void* d_out, int out_size)
{
    const float* sp     = (const float*)d_in[0];  // scaled_params (B,6)
    const float* pp     = (const float*)d_in[1];  // pred_params   (B,28)
    const float* pmean  = (const float*)d_in[2];  // (6,)
    const float* pscale = (const float*)d_in[3];  // (6,)
    const float* tmean  = (const float*)d_in[4];  // (1,)
    const float* tscale = (const float*)d_in[5];  // (1,)
    float* out = (float*)d_out;

    const int B      = in_sizes[0] / 6;
    const int ntiles = (B + ROWS - 1) / ROWS;

    // persistent grid: 8 blocks/SM on 152 SMs (GB300) -> 1216 streams
    int blocks = 152 * 8;
    if (blocks > ntiles) blocks = ntiles;
    scaled_pred_kernel<<<blocks, TPB>>>(sp, pp, pmean, pscale, tmean, tscale, out, B);
}